// round 9
// baseline (speedup 1.0000x reference)
#include <cuda_runtime.h>
#include <math.h>
#include <stdint.h>

#define E_   1024
#define NH_  8
#define HD_  128
#define BS_  2048

// ---- scratch (device globals: no allocation allowed) ----
__device__ float g_Q[BS_ * E_];
__device__ float g_K[BS_ * E_];
__device__ float g_V[BS_ * E_];
__device__ float g_Vt[NH_ * HD_ * BS_];          // per-head transposed V: [h][d][m]
__device__ float g_P[(size_t)NH_ * BS_ * BS_];   // 8 x 2048 x 2048 score/prob planes
__device__ float g_attn[BS_ * E_];
__device__ float g_h[BS_ * E_];
__device__ float g_hr[BS_ * E_];                 // tf32-rounded copy of h
__device__ float g_f1[BS_ * 4 * E_];
__device__ float g_f2[BS_ * E_];
__device__ float g_zb[4 * E_];                   // zero bias (zero-initialized)
// tf32-rounded copies of external inputs
__device__ float g_x1r[BS_ * E_];
__device__ float g_x2r[BS_ * E_];
__device__ float g_Wqr[E_ * E_];
__device__ float g_Wkr[E_ * E_];
__device__ float g_Wvr[E_ * E_];
__device__ float g_Wor[E_ * E_];
__device__ float g_W1r[4 * E_ * E_];
__device__ float g_W2r[4 * E_ * E_];

// ============================================================
// helpers: cp.async + tf32 mma.sync (base sm_103 ISA)
// ============================================================
__device__ __forceinline__ uint32_t smem_u32(const void* p) {
    uint32_t a;
    asm("{ .reg .u64 t; cvta.to.shared.u64 t, %1; cvt.u32.u64 %0, t; }" : "=r"(a) : "l"(p));
    return a;
}
__device__ __forceinline__ void cp16(uint32_t dst, const void* src) {
    asm volatile("cp.async.cg.shared.global [%0], [%1], 16;" :: "r"(dst), "l"(src));
}
#define CP_COMMIT() asm volatile("cp.async.commit_group;" ::: "memory")
#define CP_WAIT2()  asm volatile("cp.async.wait_group 2;" ::: "memory")

__device__ __forceinline__ uint32_t to_tf32(float f) {
    uint32_t r;
    asm("cvt.rna.tf32.f32 %0, %1;" : "=r"(r) : "f"(f));
    return r;
}
__device__ __forceinline__ float round_tf32f(float f) {
    return __uint_as_float(to_tf32(f));
}
__device__ __forceinline__ void mma8(float c[4], uint32_t a0, uint32_t a1,
                                     uint32_t a2, uint32_t a3,
                                     uint32_t b0, uint32_t b1) {
    asm volatile(
        "mma.sync.aligned.m16n8k8.row.col.f32.tf32.tf32.f32 "
        "{%0,%1,%2,%3}, {%4,%5,%6,%7}, {%8,%9}, {%0,%1,%2,%3};"
        : "+f"(c[0]), "+f"(c[1]), "+f"(c[2]), "+f"(c[3])
        : "r"(a0), "r"(a1), "r"(a2), "r"(a3), "r"(b0), "r"(b1));
}

// ============================================================
// elementwise tf32 round-copy
// ============================================================
__global__ __launch_bounds__(256) void round_copy(const float* __restrict__ in,
                                                  float* __restrict__ out)
{
    const size_t i = (size_t)blockIdx.x * 256 + threadIdx.x;
    float4 v = ((const float4*)in)[i];
    v.x = round_tf32f(v.x); v.y = round_tf32f(v.y);
    v.z = round_tf32f(v.z); v.w = round_tf32f(v.w);
    ((float4*)out)[i] = v;
}

// ============================================================
// Unified tf32 tensor-core NT GEMM: C = A @ B^T + bias, opt ReLU
// Inputs MUST be pre-rounded to tf32 (raw bits fed to mma).
// BM=BN=128, BK=32, 3-stage cp.async, 8 warps (2x4), warp tile 64x32.
// Grid: (N/128, M/128, Z). round_out: round result to tf32 before store.
// ============================================================
#define SROW 36
#define STAGE_F (2 * 128 * SROW)
#define GEMM_SMEM (3 * STAGE_F * 4)

__global__ __launch_bounds__(256, 2) void gemm_mma(
    const float* __restrict__ A, long long az, int lda,
    const float* __restrict__ B, long long bz, int ldb,
    const float* __restrict__ bias,
    float* __restrict__ C, long long cz, int ldc,
    int K, int relu, int round_out)
{
    extern __shared__ __align__(16) float sm[];
    const int tid = threadIdx.x;
    const int bm = blockIdx.y * 128, bn = blockIdx.x * 128;
    A += (size_t)blockIdx.z * az;
    B += (size_t)blockIdx.z * bz;
    C += (size_t)blockIdx.z * cz;

    const int lrow = tid >> 1;
    const int lhalf = (tid & 1) << 4;
    const float* gA = A + (size_t)(bm + lrow) * lda + lhalf;
    const float* gB = B + (size_t)(bn + lrow) * ldb + lhalf;
    const uint32_t sA0 = smem_u32(sm) + (uint32_t)(lrow * SROW + lhalf) * 4u;
    const uint32_t sB0 = sA0 + 128u * SROW * 4u;

    const int warp = tid >> 5, lane = tid & 31;
    const int g = lane >> 2, tig = lane & 3;
    const int am = (warp >> 2) * 64;
    const int bnw = (warp & 3) * 32;

    float acc[4][4][4];
#pragma unroll
    for (int mi = 0; mi < 4; ++mi)
#pragma unroll
        for (int ni = 0; ni < 4; ++ni)
#pragma unroll
            for (int r = 0; r < 4; ++r) acc[mi][ni][r] = 0.f;

    const int NT = K >> 5;

#pragma unroll
    for (int s = 0; s < 2; ++s) {
        const uint32_t dA = sA0 + (uint32_t)(s * STAGE_F) * 4u;
        const uint32_t dB = sB0 + (uint32_t)(s * STAGE_F) * 4u;
        const float* pa = gA + s * 32;
        const float* pb = gB + s * 32;
#pragma unroll
        for (int c = 0; c < 4; ++c) {
            cp16(dA + c * 16u, pa + c * 4);
            cp16(dB + c * 16u, pb + c * 4);
        }
        CP_COMMIT();
    }

    for (int kt = 0; kt < NT; ++kt) {
        if (kt + 2 < NT) {
            const int s = (kt + 2) % 3;
            const uint32_t dA = sA0 + (uint32_t)(s * STAGE_F) * 4u;
            const uint32_t dB = sB0 + (uint32_t)(s * STAGE_F) * 4u;
            const float* pa = gA + (kt + 2) * 32;
            const float* pb = gB + (kt + 2) * 32;
#pragma unroll
            for (int c = 0; c < 4; ++c) {
                cp16(dA + c * 16u, pa + c * 4);
                cp16(dB + c * 16u, pb + c * 4);
            }
        }
        CP_COMMIT();
        CP_WAIT2();
        __syncthreads();

        const uint32_t* As = (const uint32_t*)sm + (kt % 3) * STAGE_F;
        const uint32_t* Bs = As + 128 * SROW;

#pragma unroll
        for (int k8 = 0; k8 < 4; ++k8) {
            const int kk = k8 * 8;
            uint32_t a[4][4];
#pragma unroll
            for (int mi = 0; mi < 4; ++mi) {
                const uint32_t* p = As + (am + mi * 16 + g) * SROW + kk + tig;
                a[mi][0] = p[0];
                a[mi][2] = p[4];
                a[mi][1] = p[8 * SROW];
                a[mi][3] = p[8 * SROW + 4];
            }
            uint32_t b[4][2];
#pragma unroll
            for (int ni = 0; ni < 4; ++ni) {
                const uint32_t* q = Bs + (bnw + ni * 8 + g) * SROW + kk + tig;
                b[ni][0] = q[0];
                b[ni][1] = q[4];
            }
#pragma unroll
            for (int mi = 0; mi < 4; ++mi)
#pragma unroll
                for (int ni = 0; ni < 4; ++ni)
                    mma8(acc[mi][ni], a[mi][0], a[mi][1], a[mi][2], a[mi][3],
                         b[ni][0], b[ni][1]);
        }
        __syncthreads();
    }

#pragma unroll
    for (int mi = 0; mi < 4; ++mi) {
        const int r0 = bm + am + mi * 16 + g;
#pragma unroll
        for (int ni = 0; ni < 4; ++ni) {
            const int col = bn + bnw + ni * 8 + 2 * tig;
            const float bi0 = bias[col], bi1 = bias[col + 1];
            float v0 = acc[mi][ni][0] + bi0, v1 = acc[mi][ni][1] + bi1;
            float v2 = acc[mi][ni][2] + bi0, v3 = acc[mi][ni][3] + bi1;
            if (relu) {
                v0 = fmaxf(v0, 0.f); v1 = fmaxf(v1, 0.f);
                v2 = fmaxf(v2, 0.f); v3 = fmaxf(v3, 0.f);
            }
            if (round_out) {
                v0 = round_tf32f(v0); v1 = round_tf32f(v1);
                v2 = round_tf32f(v2); v3 = round_tf32f(v3);
            }
            float2 p0 = {v0, v1}, p1 = {v2, v3};
            *(float2*)(C + (size_t)r0 * ldc + col) = p0;
            *(float2*)(C + (size_t)(r0 + 8) * ldc + col) = p1;
        }
    }
}

// ============================================================
// V transpose: Vt[h][d][m] = V[m][h*128+d]. Grid (64,4,8), block (32,8)
// ============================================================
__global__ void vt_kernel(const float* __restrict__ V, float* __restrict__ Vt)
{
    __shared__ float t[32][33];
    const int m0 = blockIdx.x * 32, d0 = blockIdx.y * 32, h = blockIdx.z;
    const int tx = threadIdx.x, ty = threadIdx.y;
#pragma unroll
    for (int j = 0; j < 32; j += 8)
        t[ty + j][tx] = V[(size_t)(m0 + ty + j) * 1024 + h * 128 + d0 + tx];
    __syncthreads();
    float* dst = Vt + (size_t)h * 128 * 2048;
#pragma unroll
    for (int j = 0; j < 32; j += 8)
        dst[(size_t)(d0 + ty + j) * 2048 + m0 + tx] = t[tx][ty + j];
}

// ============================================================
// Softmax over the 8 head planes; writes tf32-rounded probs.
// ============================================================
__global__ __launch_bounds__(256) void softmax8(float* __restrict__ P)
{
    const size_t idx = (size_t)blockIdx.x * 256 + threadIdx.x;
    const float scale = 0.08838834764831845f;  // 1/sqrt(128)
    float4* P4 = (float4*)P;
    const size_t plane4 = (size_t)1 << 20;

    float4 v[8];
#pragma unroll
    for (int h = 0; h < 8; ++h) v[h] = P4[h * plane4 + idx];

#pragma unroll
    for (int lane = 0; lane < 4; ++lane) {
        float s[8], mx = -1e30f;
#pragma unroll
        for (int h = 0; h < 8; ++h) {
            s[h] = ((float*)&v[h])[lane] * scale;
            mx = fmaxf(mx, s[h]);
        }
        float sum = 0.f;
#pragma unroll
        for (int h = 0; h < 8; ++h) { s[h] = expf(s[h] - mx); sum += s[h]; }
        const float inv = 1.0f / sum;
#pragma unroll
        for (int h = 0; h < 8; ++h)
            ((float*)&v[h])[lane] = round_tf32f(s[h] * inv);
    }

#pragma unroll
    for (int h = 0; h < 8; ++h) P4[h * plane4 + idx] = v[h];
}

// ============================================================
// Residual + LayerNorm: Y = LN(X + R) * g + b. Optional rounded copy Yr.
// ============================================================
__global__ __launch_bounds__(256) void resid_ln(
    const float* __restrict__ X, const float* __restrict__ R,
    const float* __restrict__ g, const float* __restrict__ b,
    float* __restrict__ Y, float* __restrict__ Yr)
{
    __shared__ float red[8];
    const int row = blockIdx.x;
    const int tid = threadIdx.x;

    float4 xv = ((const float4*)(X + (size_t)row * 1024))[tid];
    float4 rv = ((const float4*)(R + (size_t)row * 1024))[tid];
    float v[4] = {xv.x + rv.x, xv.y + rv.y, xv.z + rv.z, xv.w + rv.w};

    float s = v[0] + v[1] + v[2] + v[3];
#pragma unroll
    for (int o = 16; o; o >>= 1) s += __shfl_xor_sync(0xffffffffu, s, o);
    if ((tid & 31) == 0) red[tid >> 5] = s;
    __syncthreads();
    float mean = 0.f;
#pragma unroll
    for (int w = 0; w < 8; ++w) mean += red[w];
    mean *= (1.0f / 1024.0f);

    float d0 = v[0] - mean, d1 = v[1] - mean, d2 = v[2] - mean, d3 = v[3] - mean;
    float ss = d0 * d0 + d1 * d1 + d2 * d2 + d3 * d3;
#pragma unroll
    for (int o = 16; o; o >>= 1) ss += __shfl_xor_sync(0xffffffffu, ss, o);
    __syncthreads();
    if ((tid & 31) == 0) red[tid >> 5] = ss;
    __syncthreads();
    float var = 0.f;
#pragma unroll
    for (int w = 0; w < 8; ++w) var += red[w];
    var *= (1.0f / 1024.0f);
    const float rstd = rsqrtf(var + 1e-5f);

    float4 gv = ((const float4*)g)[tid];
    float4 bv = ((const float4*)b)[tid];
    float4 o4;
    o4.x = d0 * rstd * gv.x + bv.x;
    o4.y = d1 * rstd * gv.y + bv.y;
    o4.z = d2 * rstd * gv.z + bv.z;
    o4.w = d3 * rstd * gv.w + bv.w;
    ((float4*)(Y + (size_t)row * 1024))[tid] = o4;
    if (Yr) {
        float4 r4;
        r4.x = round_tf32f(o4.x); r4.y = round_tf32f(o4.y);
        r4.z = round_tf32f(o4.z); r4.w = round_tf32f(o4.w);
        ((float4*)(Yr + (size_t)row * 1024))[tid] = r4;
    }
}

// ============================================================
extern "C" void kernel_launch(void* const* d_in, const int* in_sizes, int n_in,
                              void* d_out, int out_size)
{
    (void)in_sizes; (void)n_in; (void)out_size;
    const float* x1  = (const float*)d_in[0];
    const float* x2  = (const float*)d_in[1];
    const float* Wq  = (const float*)d_in[2];
    const float* bq  = (const float*)d_in[3];
    const float* Wk  = (const float*)d_in[4];
    const float* bk  = (const float*)d_in[5];
    const float* Wv  = (const float*)d_in[6];
    const float* bv  = (const float*)d_in[7];
    const float* Wo  = (const float*)d_in[8];
    const float* bo  = (const float*)d_in[9];
    const float* W1  = (const float*)d_in[10];
    const float* b1  = (const float*)d_in[11];
    const float* W2  = (const float*)d_in[12];
    const float* b2  = (const float*)d_in[13];
    const float* g1  = (const float*)d_in[14];
    const float* be1 = (const float*)d_in[15];
    const float* g2  = (const float*)d_in[16];
    const float* be2 = (const float*)d_in[17];
    float* out = (float*)d_out;

    float *Q, *K, *V, *Vt, *P, *attn, *hb, *hbr, *f1, *f2, *zb;
    float *x1r, *x2r, *Wqr, *Wkr, *Wvr, *Wor, *W1r, *W2r;
    cudaGetSymbolAddress((void**)&Q,    g_Q);
    cudaGetSymbolAddress((void**)&K,    g_K);
    cudaGetSymbolAddress((void**)&V,    g_V);
    cudaGetSymbolAddress((void**)&Vt,   g_Vt);
    cudaGetSymbolAddress((void**)&P,    g_P);
    cudaGetSymbolAddress((void**)&attn, g_attn);
    cudaGetSymbolAddress((void**)&hb,   g_h);
    cudaGetSymbolAddress((void**)&hbr,  g_hr);
    cudaGetSymbolAddress((void**)&f1,   g_f1);
    cudaGetSymbolAddress((void**)&f2,   g_f2);
    cudaGetSymbolAddress((void**)&zb,   g_zb);
    cudaGetSymbolAddress((void**)&x1r,  g_x1r);
    cudaGetSymbolAddress((void**)&x2r,  g_x2r);
    cudaGetSymbolAddress((void**)&Wqr,  g_Wqr);
    cudaGetSymbolAddress((void**)&Wkr,  g_Wkr);
    cudaGetSymbolAddress((void**)&Wvr,  g_Wvr);
    cudaGetSymbolAddress((void**)&Wor,  g_Wor);
    cudaGetSymbolAddress((void**)&W1r,  g_W1r);
    cudaGetSymbolAddress((void**)&W2r,  g_W2r);

    cudaFuncSetAttribute(gemm_mma, cudaFuncAttributeMaxDynamicSharedMemorySize, GEMM_SMEM);

    dim3 t256(256);

    // pre-round external GEMM operands to tf32
    round_copy<<<2048, t256>>>(x1, x1r);
    round_copy<<<2048, t256>>>(x2, x2r);
    round_copy<<<1024, t256>>>(Wq, Wqr);
    round_copy<<<1024, t256>>>(Wk, Wkr);
    round_copy<<<1024, t256>>>(Wv, Wvr);
    round_copy<<<1024, t256>>>(Wo, Wor);
    round_copy<<<4096, t256>>>(W1, W1r);
    round_copy<<<4096, t256>>>(W2, W2r);

    // QKV projections (outputs rounded for downstream GEMMs)
    gemm_mma<<<dim3(8, 16, 1), t256, GEMM_SMEM>>>(x1r, 0, 1024, Wqr, 0, 1024, bq, Q, 0, 1024, 1024, 0, 1);
    gemm_mma<<<dim3(8, 16, 1), t256, GEMM_SMEM>>>(x2r, 0, 1024, Wkr, 0, 1024, bk, K, 0, 1024, 1024, 0, 1);
    gemm_mma<<<dim3(8, 16, 1), t256, GEMM_SMEM>>>(x2r, 0, 1024, Wvr, 0, 1024, bv, V, 0, 1024, 1024, 0, 1);

    // transpose V -> Vt[h][d][m] (V already rounded)
    vt_kernel<<<dim3(64, 4, 8), dim3(32, 8)>>>(V, Vt);

    // scores per head: S_h = Q_h @ K_h^T (raw fp32; softmax rounds probs)
    gemm_mma<<<dim3(16, 16, 8), t256, GEMM_SMEM>>>(Q, 128, 1024, K, 128, 1024, zb,
                                                   P, (long long)1 << 22, 2048, 128, 0, 0);
    softmax8<<<4096, t256>>>(P);

    // attn: attn[:, h*128:(h+1)*128] = P_h @ Vt_h^T (rounded out)
    gemm_mma<<<dim3(1, 16, 8), t256, GEMM_SMEM>>>(P, (long long)1 << 22, 2048,
                                                  Vt, 128ll * 2048, 2048, zb,
                                                  attn, 128, 1024, 2048, 0, 1);

    // output projection (fp32 out; feeds LN only)
    gemm_mma<<<dim3(8, 16, 1), t256, GEMM_SMEM>>>(attn, 0, 1024, Wor, 0, 1024, bo, f2, 0, 1024, 1024, 0, 0);

    // h = LN(x1 + attnproj); also write rounded copy for FFN1
    resid_ln<<<2048, t256>>>(f2, x1, g1, be1, hb, hbr);

    // FFN
    gemm_mma<<<dim3(32, 16, 1), t256, GEMM_SMEM>>>(hbr, 0, 1024, W1r, 0, 1024, b1, f1, 0, 4096, 1024, 1, 1);
    gemm_mma<<<dim3(8, 16, 1), t256, GEMM_SMEM>>>(f1, 0, 4096, W2r, 0, 4096, b2, f2, 0, 1024, 4096, 0, 0);

    // out = LN(h + ffn)
    resid_ln<<<2048, t256>>>(f2, hb, g2, be2, out, nullptr);
}